// round 1
// baseline (speedup 1.0000x reference)
#include <cuda_runtime.h>
#include <cuda_bf16.h>

// GlobalContextBlock (GCNet) fused implementation.
// Shapes (fixed by reference): B=32, H=W=64 (HW=4096), C=256, HEADS=8, c1=32, planes=64.
//
// Pass 1 (k1): one streaming pass over x computing, per (batch, head):
//     den = sum_s exp(logit_s),  num[c] = sum_s exp(logit_s) * x[s,c]
//   (no max-subtraction: logits ~ N(0, sqrt(2)), |logit| < ~7, exp is safe in fp32)
// Pass 2 (k2): per batch: ctx = num/den; y = ctx@w1+b1; LayerNorm(eps=1e-3); ReLU;
//   term = y@w2+b2  -> g_term[b][c]
// Pass 3 (k3): out = x + term[b][c]  (streaming, float4)

#define HW    4096
#define C     256
#define C4    64
#define HEADS 8
#define C1    32
#define PLANES 64
#define NCHUNK 16          // spatial chunks per batch in k1
#define POS_PER_CHUNK (HW / NCHUNK)   // 256
#define MAXB  64

__device__ float g_pnum[MAXB * NCHUNK * C];     // partial numerators
__device__ float g_pden[MAXB * NCHUNK * HEADS]; // partial denominators
__device__ float g_term[MAXB * C];              // final additive term

// ---------------------------------------------------------------------------
// Kernel 1: softmax-weighted spatial pooling partials (one read of x).
// grid = B * NCHUNK blocks, 256 threads (8 warps).
// Warp w covers half-row (w&1): channels [half*128, half*128+128), i.e. 4 heads,
// for positions s0 + (w>>1) + 4k, k = 0..POS_PER_CHUNK/4-1.
// Lane l owns channels half*128 + 4l .. +3  (head-local channel = (4l)&31).
// ---------------------------------------------------------------------------
__global__ __launch_bounds__(256) void gc_pool_kernel(
    const float* __restrict__ x, const float* __restrict__ wm,
    const float* __restrict__ bmp)
{
    const int blk   = blockIdx.x;
    const int b     = blk / NCHUNK;
    const int chunk = blk % NCHUNK;
    const int s0    = chunk * POS_PER_CHUNK;

    const int tid  = threadIdx.x;
    const int w    = tid >> 5;
    const int l    = tid & 31;
    const int half = w & 1;
    const int wrow = w >> 1;            // 0..3

    // wm is shared across heads: index = (4l) % 32
    const float4 wmv = *reinterpret_cast<const float4*>(wm + 4 * (l & 7));
    const float  bm  = bmp[0];

    const float* base = x + ((size_t)b * HW + s0 + wrow) * C + half * 128 + 4 * l;

    float4 acc = make_float4(0.f, 0.f, 0.f, 0.f);
    float  den = 0.f;

    #pragma unroll 4
    for (int k = 0; k < POS_PER_CHUNK / 4; k++) {
        const float4 xv = *reinterpret_cast<const float4*>(base + (size_t)k * 4 * C);
        float p = xv.x * wmv.x + xv.y * wmv.y + xv.z * wmv.z + xv.w * wmv.w;
        // reduce across the 8 lanes sharing a head (low 3 lane bits)
        p += __shfl_xor_sync(0xFFFFFFFFu, p, 1);
        p += __shfl_xor_sync(0xFFFFFFFFu, p, 2);
        p += __shfl_xor_sync(0xFFFFFFFFu, p, 4);
        const float e = __expf(p + bm);
        acc.x = fmaf(e, xv.x, acc.x);
        acc.y = fmaf(e, xv.y, acc.y);
        acc.z = fmaf(e, xv.z, acc.z);
        acc.w = fmaf(e, xv.w, acc.w);
        den += e;   // same value across the 8-lane group; leader stores it
    }

    __shared__ float s_num[8][128];
    __shared__ float s_den[8][4];
    s_num[w][4 * l + 0] = acc.x;
    s_num[w][4 * l + 1] = acc.y;
    s_num[w][4 * l + 2] = acc.z;
    s_num[w][4 * l + 3] = acc.w;
    if ((l & 7) == 0) s_den[w][l >> 3] = den;
    __syncthreads();

    // combine the 4 warps per half
    {
        const int ch = tid;            // channel 0..255
        const int hf = ch >> 7;
        const int cl = ch & 127;
        const float s = s_num[hf][cl] + s_num[hf + 2][cl] +
                        s_num[hf + 4][cl] + s_num[hf + 6][cl];
        g_pnum[(size_t)blk * C + ch] = s;
    }
    if (tid < HEADS) {
        const int head = tid;
        const int hf = head >> 2;
        const int hh = head & 3;
        const float d = s_den[hf][hh] + s_den[hf + 2][hh] +
                        s_den[hf + 4][hh] + s_den[hf + 6][hh];
        g_pden[(size_t)blk * HEADS + head] = d;
    }
}

// ---------------------------------------------------------------------------
// Kernel 2: per-batch ctx + bottleneck MLP.  grid = B blocks, 256 threads.
// ---------------------------------------------------------------------------
__global__ __launch_bounds__(256) void gc_mlp_kernel(
    const float* __restrict__ w1, const float* __restrict__ b1,
    const float* __restrict__ gamma, const float* __restrict__ beta,
    const float* __restrict__ w2, const float* __restrict__ b2)
{
    const int b   = blockIdx.x;
    const int tid = threadIdx.x;

    __shared__ float s_ctx[C];
    __shared__ float s_y[PLANES];
    __shared__ float s_stats[2];

    // ctx[c] = sum_chunk num / sum_chunk den(head)
    {
        const int c = tid;
        const int head = c >> 5;
        float num = 0.f, den = 0.f;
        #pragma unroll
        for (int ch = 0; ch < NCHUNK; ch++) {
            num += g_pnum[((size_t)b * NCHUNK + ch) * C + c];
            den += g_pden[((size_t)b * NCHUNK + ch) * HEADS + head];
        }
        s_ctx[c] = num / den;
    }
    __syncthreads();

    // y[p] = ctx @ w1 + b1 : 4 threads per output plane
    {
        const int p = tid >> 2;     // 0..63
        const int q = tid & 3;
        float acc = 0.f;
        #pragma unroll 8
        for (int i = 0; i < 64; i++) {
            const int c = q * 64 + i;
            acc = fmaf(s_ctx[c], w1[c * PLANES + p], acc);
        }
        acc += __shfl_xor_sync(0xFFFFFFFFu, acc, 1);
        acc += __shfl_xor_sync(0xFFFFFFFFu, acc, 2);
        if (q == 0) s_y[p] = acc + b1[p];
    }
    __syncthreads();

    // LayerNorm stats over 64 planes (warp 0)
    if (tid < 32) {
        const float v1 = s_y[tid];
        const float v2 = s_y[tid + 32];
        float s  = v1 + v2;
        float sq = v1 * v1 + v2 * v2;
        #pragma unroll
        for (int m = 16; m > 0; m >>= 1) {
            s  += __shfl_xor_sync(0xFFFFFFFFu, s,  m);
            sq += __shfl_xor_sync(0xFFFFFFFFu, sq, m);
        }
        if (tid == 0) {
            const float mean = s / 64.f;
            const float var  = sq / 64.f - mean * mean;
            s_stats[0] = mean;
            s_stats[1] = rsqrtf(var + 1e-3f);
        }
    }
    __syncthreads();

    // normalize + relu
    if (tid < PLANES) {
        const float mean = s_stats[0], rstd = s_stats[1];
        float v = (s_y[tid] - mean) * rstd * gamma[tid] + beta[tid];
        s_y[tid] = fmaxf(v, 0.f);
    }
    __syncthreads();

    // term[c] = y @ w2 + b2
    {
        const int c = tid;
        float acc = b2[c];
        #pragma unroll 8
        for (int p = 0; p < PLANES; p++)
            acc = fmaf(s_y[p], w2[p * C + c], acc);
        g_term[(size_t)b * C + c] = acc;
    }
}

// ---------------------------------------------------------------------------
// Kernel 3: out = x + term[b][c]   (streaming float4)
// ---------------------------------------------------------------------------
__global__ __launch_bounds__(256) void gc_add_kernel(
    const float4* __restrict__ x4, float4* __restrict__ out4, int n4)
{
    const int i = blockIdx.x * blockDim.x + threadIdx.x;
    if (i >= n4) return;
    const int c4 = i & (C4 - 1);
    const int b  = i >> 18;                 // HW*C/4 = 2^18 per batch
    const float4 t = reinterpret_cast<const float4*>(g_term)[b * C4 + c4];
    float4 v = x4[i];
    v.x += t.x; v.y += t.y; v.z += t.z; v.w += t.w;
    out4[i] = v;
}

extern "C" void kernel_launch(void* const* d_in, const int* in_sizes, int n_in,
                              void* d_out, int out_size)
{
    const float* x     = (const float*)d_in[0];
    const float* wm    = (const float*)d_in[1];
    const float* bm    = (const float*)d_in[2];
    const float* w1    = (const float*)d_in[3];
    const float* b1    = (const float*)d_in[4];
    const float* gamma = (const float*)d_in[5];
    const float* beta  = (const float*)d_in[6];
    const float* w2    = (const float*)d_in[7];
    const float* b2    = (const float*)d_in[8];
    float* out = (float*)d_out;

    const int B = in_sizes[0] / (HW * C);

    gc_pool_kernel<<<B * NCHUNK, 256>>>(x, wm, bm);
    gc_mlp_kernel<<<B, 256>>>(w1, b1, gamma, beta, w2, b2);

    const int n4 = out_size / 4;
    gc_add_kernel<<<(n4 + 255) / 256, 256>>>(
        (const float4*)x, (float4*)out, n4);
}

// round 2
// speedup vs baseline: 1.0999x; 1.0999x over previous
#include <cuda_runtime.h>
#include <cuda_bf16.h>

// GlobalContextBlock (GCNet) fused implementation. Shapes fixed:
// B=32, H=W=64 (HW=4096), C=256, HEADS=8, c1=32, planes=64.
//
// k1: one streaming pass over x: per (batch, head) den = sum exp(logit),
//     num[c] = sum exp(logit)*x  (safe without max-subtraction: |logit|<~7)
// k2: per batch: ctx = num/den; MLP(256->64, LN eps=1e-3, ReLU, 64->256) -> term
// k3: out = x + term[b][c]

#define HW    4096
#define C     256
#define C4    64
#define HEADS 8
#define PLANES 64
#define NCHUNK 32                      // spatial chunks per batch in k1
#define POS_PER_CHUNK (HW / NCHUNK)    // 128
#define MAXB  64

__device__ float g_pnum[MAXB * NCHUNK * C];
__device__ float g_pden[MAXB * NCHUNK * HEADS];
__device__ float g_term[MAXB * C];

// ---------------------------------------------------------------------------
// Kernel 1: softmax-weighted spatial pooling partials (single read of x).
// grid = B*NCHUNK blocks, 256 threads (8 warps).
// Warp w: half = w&1 -> channels [half*128, half*128+128) (4 heads);
// positions s0 + (w>>1) + 4k. Lane l owns channels half*128 + 4l..4l+3.
// Inner loop batches UB=8 independent positions to raise MLP.
// ---------------------------------------------------------------------------
#define UB 8
__global__ __launch_bounds__(256) void gc_pool_kernel(
    const float* __restrict__ x, const float* __restrict__ wm,
    const float* __restrict__ bmp)
{
    const int blk   = blockIdx.x;
    const int b     = blk / NCHUNK;
    const int chunk = blk % NCHUNK;
    const int s0    = chunk * POS_PER_CHUNK;

    const int tid  = threadIdx.x;
    const int w    = tid >> 5;
    const int l    = tid & 31;
    const int half = w & 1;
    const int wrow = w >> 1;            // 0..3

    const float4 wmv = *reinterpret_cast<const float4*>(wm + 4 * (l & 7));
    const float  bm  = bmp[0];

    const float* base = x + ((size_t)b * HW + s0 + wrow) * C + half * 128 + 4 * l;

    float4 acc = make_float4(0.f, 0.f, 0.f, 0.f);
    float  den = 0.f;

    // POS_PER_CHUNK/4 = 32 positions per warp, in 4 batches of UB=8.
    #pragma unroll
    for (int kk = 0; kk < POS_PER_CHUNK / 4 / UB; kk++) {
        float4 xv[UB];
        #pragma unroll
        for (int u = 0; u < UB; u++)
            xv[u] = *reinterpret_cast<const float4*>(
                base + (size_t)(kk * UB + u) * 4 * C);

        float p[UB];
        #pragma unroll
        for (int u = 0; u < UB; u++)
            p[u] = xv[u].x * wmv.x + xv[u].y * wmv.y +
                   xv[u].z * wmv.z + xv[u].w * wmv.w;

        // independent shfl chains pipeline across the 8 positions
        #pragma unroll
        for (int u = 0; u < UB; u++) p[u] += __shfl_xor_sync(0xFFFFFFFFu, p[u], 1);
        #pragma unroll
        for (int u = 0; u < UB; u++) p[u] += __shfl_xor_sync(0xFFFFFFFFu, p[u], 2);
        #pragma unroll
        for (int u = 0; u < UB; u++) p[u] += __shfl_xor_sync(0xFFFFFFFFu, p[u], 4);

        float e[UB];
        #pragma unroll
        for (int u = 0; u < UB; u++) e[u] = __expf(p[u] + bm);

        #pragma unroll
        for (int u = 0; u < UB; u++) {
            acc.x = fmaf(e[u], xv[u].x, acc.x);
            acc.y = fmaf(e[u], xv[u].y, acc.y);
            acc.z = fmaf(e[u], xv[u].z, acc.z);
            acc.w = fmaf(e[u], xv[u].w, acc.w);
            den  += e[u];
        }
    }

    __shared__ float s_num[8][128];
    __shared__ float s_den[8][4];
    s_num[w][4 * l + 0] = acc.x;
    s_num[w][4 * l + 1] = acc.y;
    s_num[w][4 * l + 2] = acc.z;
    s_num[w][4 * l + 3] = acc.w;
    if ((l & 7) == 0) s_den[w][l >> 3] = den;
    __syncthreads();

    {
        const int ch = tid;            // 0..255
        const int hf = ch >> 7;
        const int cl = ch & 127;
        g_pnum[(size_t)blk * C + ch] =
            s_num[hf][cl] + s_num[hf + 2][cl] + s_num[hf + 4][cl] + s_num[hf + 6][cl];
    }
    if (tid < HEADS) {
        const int hf = tid >> 2;
        const int hh = tid & 3;
        g_pden[(size_t)blk * HEADS + tid] =
            s_den[hf][hh] + s_den[hf + 2][hh] + s_den[hf + 4][hh] + s_den[hf + 6][hh];
    }
}

// ---------------------------------------------------------------------------
// Kernel 2: per-batch ctx + bottleneck MLP. grid = B, 256 threads.
// ---------------------------------------------------------------------------
__global__ __launch_bounds__(256) void gc_mlp_kernel(
    const float* __restrict__ w1, const float* __restrict__ b1,
    const float* __restrict__ gamma, const float* __restrict__ beta,
    const float* __restrict__ w2, const float* __restrict__ b2)
{
    const int b   = blockIdx.x;
    const int tid = threadIdx.x;

    __shared__ float s_ctx[C];
    __shared__ float s_y[PLANES];
    __shared__ float s_stats[2];

    {
        const int c = tid;
        const int head = c >> 5;
        float num = 0.f, den = 0.f;
        #pragma unroll
        for (int ch = 0; ch < NCHUNK; ch++) {
            num += g_pnum[((size_t)b * NCHUNK + ch) * C + c];
            den += g_pden[((size_t)b * NCHUNK + ch) * HEADS + head];
        }
        s_ctx[c] = num / den;
    }
    __syncthreads();

    {
        const int p = tid >> 2;
        const int q = tid & 3;
        float acc = 0.f;
        #pragma unroll 8
        for (int i = 0; i < 64; i++) {
            const int c = q * 64 + i;
            acc = fmaf(s_ctx[c], w1[c * PLANES + p], acc);
        }
        acc += __shfl_xor_sync(0xFFFFFFFFu, acc, 1);
        acc += __shfl_xor_sync(0xFFFFFFFFu, acc, 2);
        if (q == 0) s_y[p] = acc + b1[p];
    }
    __syncthreads();

    if (tid < 32) {
        const float v1 = s_y[tid];
        const float v2 = s_y[tid + 32];
        float s  = v1 + v2;
        float sq = v1 * v1 + v2 * v2;
        #pragma unroll
        for (int m = 16; m > 0; m >>= 1) {
            s  += __shfl_xor_sync(0xFFFFFFFFu, s,  m);
            sq += __shfl_xor_sync(0xFFFFFFFFu, sq, m);
        }
        if (tid == 0) {
            const float mean = s / 64.f;
            const float var  = sq / 64.f - mean * mean;
            s_stats[0] = mean;
            s_stats[1] = rsqrtf(var + 1e-3f);
        }
    }
    __syncthreads();

    if (tid < PLANES) {
        const float mean = s_stats[0], rstd = s_stats[1];
        float v = (s_y[tid] - mean) * rstd * gamma[tid] + beta[tid];
        s_y[tid] = fmaxf(v, 0.f);
    }
    __syncthreads();

    {
        const int c = tid;
        float acc = b2[c];
        #pragma unroll 8
        for (int p = 0; p < PLANES; p++)
            acc = fmaf(s_y[p], w2[p * C + c], acc);
        g_term[(size_t)b * C + c] = acc;
    }
}

// ---------------------------------------------------------------------------
// Kernel 3: out = x + term[b][c] (streaming float4 with evict-first hints)
// ---------------------------------------------------------------------------
__global__ __launch_bounds__(512) void gc_add_kernel(
    const float4* __restrict__ x4, float4* __restrict__ out4, int n4)
{
    const int i = blockIdx.x * blockDim.x + threadIdx.x;
    if (i >= n4) return;
    const int c4 = i & (C4 - 1);
    const int b  = i >> 18;                 // HW*C/4 = 2^18 float4 per batch
    const float4 t = reinterpret_cast<const float4*>(g_term)[b * C4 + c4];
    float4 v = __ldcs(x4 + i);
    v.x += t.x; v.y += t.y; v.z += t.z; v.w += t.w;
    __stcs(out4 + i, v);
}

extern "C" void kernel_launch(void* const* d_in, const int* in_sizes, int n_in,
                              void* d_out, int out_size)
{
    const float* x     = (const float*)d_in[0];
    const float* wm    = (const float*)d_in[1];
    const float* bm    = (const float*)d_in[2];
    const float* w1    = (const float*)d_in[3];
    const float* b1    = (const float*)d_in[4];
    const float* gamma = (const float*)d_in[5];
    const float* beta  = (const float*)d_in[6];
    const float* w2    = (const float*)d_in[7];
    const float* b2    = (const float*)d_in[8];
    float* out = (float*)d_out;

    const int B = in_sizes[0] / (HW * C);

    gc_pool_kernel<<<B * NCHUNK, 256>>>(x, wm, bm);
    gc_mlp_kernel<<<B, 256>>>(w1, b1, gamma, beta, w2, b2);

    const int n4 = out_size / 4;
    gc_add_kernel<<<(n4 + 511) / 512, 512>>>(
        (const float4*)x, (float4*)out, n4);
}